// round 15
// baseline (speedup 1.0000x reference)
#include <cuda_runtime.h>
#include <cuda_bf16.h>
#include <cstdint>

#define BATCH 4
#define SEQ   2048
#define EMB   1024
#define NH    16
#define HD    64

// ---------------------------------------------------------------------------
// Scratch (__device__ globals; referenced ONLY from device code)
// ---------------------------------------------------------------------------
__device__ __align__(16) __nv_bfloat16 g_xhi[(size_t)BATCH * SEQ * EMB];
__device__ __align__(16) __nv_bfloat16 g_xlo[(size_t)BATCH * SEQ * EMB];
__device__ __align__(16) __nv_bfloat16 g_ahi[(size_t)BATCH * SEQ * EMB];
__device__ __align__(16) __nv_bfloat16 g_alo[(size_t)BATCH * SEQ * EMB];
__device__ __align__(16) __nv_bfloat16 g_qhi[(size_t)BATCH * NH * SEQ * HD];
__device__ __align__(16) __nv_bfloat16 g_qlo[(size_t)BATCH * NH * SEQ * HD];
__device__ __align__(16) __nv_bfloat16 g_khi[(size_t)BATCH * NH * SEQ * HD];
__device__ __align__(16) __nv_bfloat16 g_klo[(size_t)BATCH * NH * SEQ * HD];
__device__ __align__(16) __nv_bfloat16 g_vthi[(size_t)BATCH * NH * HD * SEQ];
__device__ __align__(16) __nv_bfloat16 g_vtlo[(size_t)BATCH * NH * HD * SEQ];
__device__ __align__(16) __nv_bfloat16 g_bqkv_hi[(size_t)3 * NH * HD * EMB];
__device__ __align__(16) __nv_bfloat16 g_bqkv_lo[(size_t)3 * NH * HD * EMB];
__device__ __align__(16) __nv_bfloat16 g_bp_hi[(size_t)EMB * EMB];
__device__ __align__(16) __nv_bfloat16 g_bp_lo[(size_t)EMB * EMB];

// ---------------------------------------------------------------------------
// Helpers
// ---------------------------------------------------------------------------
__device__ __forceinline__ void split1(float v, __nv_bfloat16& h, __nv_bfloat16& l) {
    h = __float2bfloat16(v);
    l = __float2bfloat16(v - __bfloat162float(h));
}
__device__ __forceinline__ void split2(float x, float y, uint32_t& hp, uint32_t& lp) {
    __nv_bfloat16 hx = __float2bfloat16(x), hy = __float2bfloat16(y);
    __nv_bfloat16 lx = __float2bfloat16(x - __bfloat162float(hx));
    __nv_bfloat16 ly = __float2bfloat16(y - __bfloat162float(hy));
    hp = (uint32_t)__bfloat16_as_ushort(hx) | ((uint32_t)__bfloat16_as_ushort(hy) << 16);
    lp = (uint32_t)__bfloat16_as_ushort(lx) | ((uint32_t)__bfloat16_as_ushort(ly) << 16);
}
__device__ __forceinline__ uint32_t smem_u32(const void* p) {
    uint32_t a;
    asm("{ .reg .u64 t; cvta.to.shared.u64 t, %1; cvt.u32.u64 %0, t; }" : "=r"(a) : "l"(p));
    return a;
}
__device__ __forceinline__ void ldsm_x4(uint32_t* r, uint32_t addr) {
    asm volatile("ldmatrix.sync.aligned.m8n8.x4.shared.b16 {%0,%1,%2,%3}, [%4];"
        : "=r"(r[0]), "=r"(r[1]), "=r"(r[2]), "=r"(r[3]) : "r"(addr));
}
__device__ __forceinline__ void mma_bf16(float* c, const uint32_t* a,
                                         uint32_t b0, uint32_t b1) {
    asm volatile("mma.sync.aligned.m16n8k16.row.col.f32.bf16.bf16.f32 "
        "{%0,%1,%2,%3}, {%4,%5,%6,%7}, {%8,%9}, {%0,%1,%2,%3};"
        : "+f"(c[0]), "+f"(c[1]), "+f"(c[2]), "+f"(c[3])
        : "r"(a[0]), "r"(a[1]), "r"(a[2]), "r"(a[3]), "r"(b0), "r"(b1));
}
__device__ __forceinline__ void cpa16(uint32_t s, const void* g) {
    asm volatile("cp.async.ca.shared.global [%0], [%1], 16;" :: "r"(s), "l"(g));
}
#define CP_COMMIT() asm volatile("cp.async.commit_group;" ::: "memory")
#define CP_WAIT0()  asm volatile("cp.async.wait_group 0;" ::: "memory")

union BF4 { __nv_bfloat16 b[4]; uint2 u; };

// ---------------------------------------------------------------------------
// Conversions (unchanged, validated)
// ---------------------------------------------------------------------------
__global__ void split_x(const float* __restrict__ in)
{
    int i = blockIdx.x * 256 + threadIdx.x;
    float4 v = ((const float4*)in)[i];
    BF4 hh, ll;
    split1(v.x, hh.b[0], ll.b[0]); split1(v.y, hh.b[1], ll.b[1]);
    split1(v.z, hh.b[2], ll.b[2]); split1(v.w, hh.b[3], ll.b[3]);
    ((uint2*)g_xhi)[i] = hh.u;
    ((uint2*)g_xlo)[i] = ll.u;
}

__global__ void conv_wqkv(const float* __restrict__ Wq,
                          const float* __restrict__ Wk,
                          const float* __restrict__ Wv)
{
    int n = blockIdx.x;
    int which = n >> 10, h = (n >> 6) & 15, d = n & 63;
    const float* W = (which == 0) ? Wq : (which == 1) ? Wk : Wv;
    for (int e = threadIdx.x; e < EMB; e += 256) {
        float v = W[((size_t)h * EMB + e) * HD + d];
        __nv_bfloat16 hh, ll;
        split1(v, hh, ll);
        g_bqkv_hi[(size_t)n * EMB + e] = hh;
        g_bqkv_lo[(size_t)n * EMB + e] = ll;
    }
}

__global__ void conv_wp(const float* __restrict__ Wp)
{
    __shared__ float t[32][33];
    int n0 = blockIdx.x * 32, k0 = blockIdx.y * 32;
    for (int r = threadIdx.y; r < 32; r += 8)
        t[r][threadIdx.x] = Wp[(size_t)(k0 + r) * EMB + n0 + threadIdx.x];
    __syncthreads();
    for (int r = threadIdx.y; r < 32; r += 8) {
        float v = t[threadIdx.x][r];
        __nv_bfloat16 hh, ll;
        split1(v, hh, ll);
        g_bp_hi[(size_t)(n0 + r) * EMB + k0 + threadIdx.x] = hh;
        g_bp_lo[(size_t)(n0 + r) * EMB + k0 + threadIdx.x] = ll;
    }
}

// ---------------------------------------------------------------------------
// Split-precision bf16 HMMA GEMM, 128x128 block tile, cp.async 2-stage pipe.
// __launch_bounds__(256, 2): cap regs at 128 so 2 CTAs co-reside per SM
// (R14 ran 134 regs -> 1 CTA/SM -> occ 12.5%, cancelling the pipe win).
// ---------------------------------------------------------------------------
#define S_AH_B  0
#define S_AL_B  10240
#define S_BH_B  20480
#define S_BL_B  30720
#define STAGE_B 40960
#define GEMM_SMEM (2 * STAGE_B)   // 81920 B
#define NKT 32                    // 1024 / 32

__global__ void __launch_bounds__(256, 2) hmma_gemm(
    const float* __restrict__ bias,
    float* __restrict__ outp, int mode)
{
    extern __shared__ __align__(16) __nv_bfloat16 sm[];
    const int tid = threadIdx.x, wid = tid >> 5, lane = tid & 31;
    const int wm = wid & 1, wn = wid >> 1;          // 2 x 4 warp grid
    const int m0 = blockIdx.x * 128, n0 = blockIdx.y * 128;

    const __nv_bfloat16* __restrict__ Ahi = (mode == 0) ? g_xhi : g_ahi;
    const __nv_bfloat16* __restrict__ Alo = (mode == 0) ? g_xlo : g_alo;
    const __nv_bfloat16* __restrict__ Bhi = (mode == 0) ? g_bqkv_hi : g_bp_hi;
    const __nv_bfloat16* __restrict__ Blo = (mode == 0) ? g_bqkv_lo : g_bp_lo;

    const uint32_t sb = smem_u32(sm);

    // Staging indices: thread -> row = tid>>2 (4 uint4 per row), c = tid&3
    const int st_row = tid >> 2, st_c = tid & 3;
    const uint32_t st_dst = st_row * 80 + st_c * 16;     // byte offset in operand
    const size_t gA0 = (size_t)(m0 + st_row) * 128 + st_c;   // uint4 units, + kt*4
    const size_t gA1 = (size_t)(m0 + st_row + 64) * 128 + st_c;
    const size_t gB0 = (size_t)(n0 + st_row) * 128 + st_c;
    const size_t gB1 = (size_t)(n0 + st_row + 64) * 128 + st_c;
    const uint32_t st_dst1 = st_dst + 64 * 80;

    // ldmatrix lane addressing (byte offsets; validated fragment layouts)
    const uint32_t a_row = wm * 64 + ((lane >> 3) & 1) * 8 + (lane & 7);
    const uint32_t a_off = a_row * 80 + ((lane >> 4) & 1) * 16;      // + mt*1280 + ks*32
    const uint32_t b_row = wn * 32 + ((lane >> 4) & 1) * 8 + (lane & 7);
    const uint32_t b_off = b_row * 80 + ((lane >> 3) & 1) * 16;      // + g16*1280 + ks*32

    float acc[4][4][4];
#pragma unroll
    for (int mt = 0; mt < 4; ++mt)
#pragma unroll
        for (int nt = 0; nt < 4; ++nt)
#pragma unroll
            for (int i = 0; i < 4; ++i) acc[mt][nt][i] = 0.f;

    // ---- prologue: stage 0 ----
    {
        uint32_t so = sb;
        cpa16(so + S_AH_B + st_dst,  (const uint4*)Ahi + gA0);
        cpa16(so + S_AH_B + st_dst1, (const uint4*)Ahi + gA1);
        cpa16(so + S_AL_B + st_dst,  (const uint4*)Alo + gA0);
        cpa16(so + S_AL_B + st_dst1, (const uint4*)Alo + gA1);
        cpa16(so + S_BH_B + st_dst,  (const uint4*)Bhi + gB0);
        cpa16(so + S_BH_B + st_dst1, (const uint4*)Bhi + gB1);
        cpa16(so + S_BL_B + st_dst,  (const uint4*)Blo + gB0);
        cpa16(so + S_BL_B + st_dst1, (const uint4*)Blo + gB1);
        CP_COMMIT();
    }

    for (int kt = 0; kt < NKT; ++kt) {
        CP_WAIT0();
        __syncthreads();
        if (kt + 1 < NKT) {                 // prefetch next slab into other buffer
            uint32_t so = sb + ((kt + 1) & 1) * STAGE_B;
            size_t ko = (size_t)(kt + 1) * 4;
            cpa16(so + S_AH_B + st_dst,  (const uint4*)Ahi + gA0 + ko);
            cpa16(so + S_AH_B + st_dst1, (const uint4*)Ahi + gA1 + ko);
            cpa16(so + S_AL_B + st_dst,  (const uint4*)Alo + gA0 + ko);
            cpa16(so + S_AL_B + st_dst1, (const uint4*)Alo + gA1 + ko);
            cpa16(so + S_BH_B + st_dst,  (const uint4*)Bhi + gB0 + ko);
            cpa16(so + S_BH_B + st_dst1, (const uint4*)Bhi + gB1 + ko);
            cpa16(so + S_BL_B + st_dst,  (const uint4*)Blo + gB0 + ko);
            cpa16(so + S_BL_B + st_dst1, (const uint4*)Blo + gB1 + ko);
            CP_COMMIT();
        }

        uint32_t so = sb + (kt & 1) * STAGE_B;
#pragma unroll
        for (int ks = 0; ks < 2; ++ks) {
            uint32_t aH[4][4], aL[4][4], bH[2][4], bL[2][4];
#pragma unroll
            for (int mt = 0; mt < 4; ++mt) {
                uint32_t off = mt * 1280 + ks * 32;
                ldsm_x4(aH[mt], so + S_AH_B + a_off + off);
                ldsm_x4(aL[mt], so + S_AL_B + a_off + off);
            }
#pragma unroll
            for (int g16 = 0; g16 < 2; ++g16) {
                uint32_t off = g16 * 1280 + ks * 32;
                ldsm_x4(bH[g16], so + S_BH_B + b_off + off);
                ldsm_x4(bL[g16], so + S_BL_B + b_off + off);
            }
#pragma unroll
            for (int mt = 0; mt < 4; ++mt)
#pragma unroll
                for (int nt = 0; nt < 4; ++nt) {
                    uint32_t h0 = bH[nt >> 1][(nt & 1) * 2], h1 = bH[nt >> 1][(nt & 1) * 2 + 1];
                    uint32_t l0 = bL[nt >> 1][(nt & 1) * 2], l1 = bL[nt >> 1][(nt & 1) * 2 + 1];
                    mma_bf16(acc[mt][nt], aH[mt], h0, h1);
                    mma_bf16(acc[mt][nt], aH[mt], l0, l1);
                    mma_bf16(acc[mt][nt], aL[mt], h0, h1);
                }
        }
    }

    // ---- epilogue ----
    const int gr = lane >> 2, cp = (lane & 3) * 2;
#pragma unroll
    for (int mt = 0; mt < 4; ++mt)
#pragma unroll
        for (int nt = 0; nt < 4; ++nt) {
            int ng = n0 + wn * 32 + nt * 8 + cp;
#pragma unroll
            for (int half = 0; half < 2; ++half) {
                int m = m0 + wm * 64 + mt * 16 + gr + half * 8;
                float2 v = make_float2(acc[mt][nt][half * 2], acc[mt][nt][half * 2 + 1]);
                if (mode == 1) {
                    v.x += bias[ng]; v.y += bias[ng + 1];
                    *(float2*)(outp + (size_t)m * EMB + ng) = v;
                } else {
                    int which = ng >> 10, h = (ng >> 6) & 15, d = ng & 63;
                    int b = m >> 11, s = m & 2047;
                    size_t bh = (size_t)b * NH + h;
                    if (which == 0) {
                        uint32_t ph, pl;
                        split2(v.x * 0.125f, v.y * 0.125f, ph, pl);
                        size_t idx = (bh * SEQ + s) * HD + d;
                        *(uint32_t*)&g_qhi[idx] = ph;
                        *(uint32_t*)&g_qlo[idx] = pl;
                    } else if (which == 1) {
                        uint32_t ph, pl;
                        split2(v.x, v.y, ph, pl);
                        size_t idx = (bh * SEQ + s) * HD + d;
                        *(uint32_t*)&g_khi[idx] = ph;
                        *(uint32_t*)&g_klo[idx] = pl;
                    } else {
                        __nv_bfloat16 hx, lx, hy, ly;
                        split1(v.x, hx, lx); split1(v.y, hy, ly);
                        size_t i0 = (bh * HD + d) * SEQ + s;
                        g_vthi[i0] = hx;       g_vtlo[i0] = lx;
                        g_vthi[i0 + SEQ] = hy; g_vtlo[i0 + SEQ] = ly;
                    }
                }
            }
        }
}

// ---------------------------------------------------------------------------
// HMMA causal flash attention, 128-row Q tiles (per-warp math identical to
// the R11-validated kernel). grid (S/128, H, B), 256 threads = 8 warps.
// 73728 B smem -> 3 CTAs/SM (37.5% occ) and half the KV staging of R11.
// ---------------------------------------------------------------------------
#define ARS 72
#define A_QH 0
#define A_QL 9216
#define A_KH 18432
#define A_KL 23040
#define A_VH 27648
#define A_VL 32256
#define ATTN_SMEM (36864 * 2)   // 73728 B

__global__ __launch_bounds__(256) void attn_hmma()
{
    extern __shared__ __align__(16) __nv_bfloat16 sh[];
    const int tid = threadIdx.x, warp = tid >> 5, lane = tid & 31;
    const int qb = blockIdx.x, h = blockIdx.y, b = blockIdx.z;
    const size_t bh = (size_t)b * NH + h;
    const int q0 = qb * 128;
    const int g = lane >> 2, tg = lane & 3;

    const int a_row = warp * 16 + ((lane >> 3) & 1) * 8 + (lane & 7);
    const int a_kof = ((lane >> 4) & 1) * 8;
    const int b_sub = ((lane >> 4) & 1) * 8 + (lane & 7);
    const int b_kof = ((lane >> 3) & 1) * 8;
    const uint32_t sb = smem_u32(sh);
    const uint32_t adrQH = sb + (A_QH + a_row * ARS + a_kof) * 2;
    const uint32_t adrQL = sb + (A_QL + a_row * ARS + a_kof) * 2;
    const uint32_t adrKH = sb + (A_KH + b_sub * ARS + b_kof) * 2;
    const uint32_t adrKL = sb + (A_KL + b_sub * ARS + b_kof) * 2;
    const uint32_t adrVH = sb + (A_VH + b_sub * ARS + b_kof) * 2;
    const uint32_t adrVL = sb + (A_VL + b_sub * ARS + b_kof) * 2;

    // Stage Q tile (128 rows, hi/lo)
    {
        const uint4* qh4 = (const uint4*)g_qhi + (bh * SEQ + q0) * 8;
        const uint4* ql4 = (const uint4*)g_qlo + (bh * SEQ + q0) * 8;
        uint4* dh = (uint4*)(sh + A_QH);
        uint4* dl = (uint4*)(sh + A_QL);
        for (int i = tid; i < 1024; i += 256) {
            int row = i >> 3, c = i & 7;
            dh[row * 9 + c] = qh4[row * 8 + c];
            dl[row * 9 + c] = ql4[row * 8 + c];
        }
    }

    float o[8][4];
#pragma unroll
    for (int nt = 0; nt < 8; ++nt)
#pragma unroll
        for (int i = 0; i < 4; ++i) o[nt][i] = 0.f;
    float mi0 = -1e30f, mi1 = -1e30f, li0 = 0.f, li1 = 0.f;

    const int njt = 2 * qb + 2;            // KV tiles of 64 keys
    for (int j = 0; j < njt; ++j) {
        __syncthreads();
        {
            const uint4* kh4 = (const uint4*)g_khi + (bh * SEQ + j * 64) * 8;
            const uint4* kl4 = (const uint4*)g_klo + (bh * SEQ + j * 64) * 8;
            const uint4* vh4 = (const uint4*)g_vthi + bh * HD * 256 + j * 8;
            const uint4* vl4 = (const uint4*)g_vtlo + bh * HD * 256 + j * 8;
            uint4* dkh = (uint4*)(sh + A_KH);
            uint4* dkl = (uint4*)(sh + A_KL);
            uint4* dvh = (uint4*)(sh + A_VH);
            uint4* dvl = (uint4*)(sh + A_VL);
            for (int i = tid; i < 512; i += 256) {
                int row = i >> 3, c = i & 7;
                dkh[row * 9 + c] = kh4[row * 8 + c];
                dkl[row * 9 + c] = kl4[row * 8 + c];
                dvh[row * 9 + c] = vh4[row * 256 + c];
                dvl[row * 9 + c] = vl4[row * 256 + c];
            }
        }
        __syncthreads();

        // ---- S = Q K^T (3-MMA split) ----
        float s[8][4];
#pragma unroll
        for (int nt = 0; nt < 8; ++nt)
#pragma unroll
            for (int i = 0; i < 4; ++i) s[nt][i] = 0.f;

#pragma unroll
        for (int ks = 0; ks < 4; ++ks) {
            uint32_t qh[4], ql[4];
            ldsm_x4(qh, adrQH + ks * 32);
            ldsm_x4(ql, adrQL + ks * 32);
#pragma unroll
            for (int g16 = 0; g16 < 4; ++g16) {
                uint32_t kh[4], kl[4];
                uint32_t go = g16 * (16 * ARS * 2);
                ldsm_x4(kh, adrKH + go + ks * 32);
                ldsm_x4(kl, adrKL + go + ks * 32);
#pragma unroll
                for (int sn = 0; sn < 2; ++sn) {
                    int nt = g16 * 2 + sn;
                    mma_bf16(s[nt], qh, kh[sn * 2], kh[sn * 2 + 1]);
                    mma_bf16(s[nt], qh, kl[sn * 2], kl[sn * 2 + 1]);
                    mma_bf16(s[nt], ql, kh[sn * 2], kh[sn * 2 + 1]);
                }
            }
        }

        // ---- causal mask (last two KV tiles only) ----
        if (j >= 2 * qb) {
            int r0 = q0 + warp * 16 + g, r1 = r0 + 8;
#pragma unroll
            for (int nt = 0; nt < 8; ++nt) {
                int c0 = j * 64 + nt * 8 + tg * 2;
                if (c0 > r0)     s[nt][0] = -1e30f;
                if (c0 + 1 > r0) s[nt][1] = -1e30f;
                if (c0 > r1)     s[nt][2] = -1e30f;
                if (c0 + 1 > r1) s[nt][3] = -1e30f;
            }
        }

        // ---- online softmax (rows r0, r1; reduce across 4-lane group) ----
        float mx0 = -1e30f, mx1 = -1e30f;
#pragma unroll
        for (int nt = 0; nt < 8; ++nt) {
            mx0 = fmaxf(mx0, fmaxf(s[nt][0], s[nt][1]));
            mx1 = fmaxf(mx1, fmaxf(s[nt][2], s[nt][3]));
        }
        mx0 = fmaxf(mx0, __shfl_xor_sync(0xffffffffu, mx0, 1));
        mx0 = fmaxf(mx0, __shfl_xor_sync(0xffffffffu, mx0, 2));
        mx1 = fmaxf(mx1, __shfl_xor_sync(0xffffffffu, mx1, 1));
        mx1 = fmaxf(mx1, __shfl_xor_sync(0xffffffffu, mx1, 2));
        float mn0 = fmaxf(mi0, mx0), mn1 = fmaxf(mi1, mx1);
        float al0 = __expf(mi0 - mn0), al1 = __expf(mi1 - mn1);
        mi0 = mn0; mi1 = mn1;
        float ls0 = 0.f, ls1 = 0.f;
#pragma unroll
        for (int nt = 0; nt < 8; ++nt) {
            s[nt][0] = __expf(s[nt][0] - mn0); ls0 += s[nt][0];
            s[nt][1] = __expf(s[nt][1] - mn0); ls0 += s[nt][1];
            s[nt][2] = __expf(s[nt][2] - mn1); ls1 += s[nt][2];
            s[nt][3] = __expf(s[nt][3] - mn1); ls1 += s[nt][3];
        }
        ls0 += __shfl_xor_sync(0xffffffffu, ls0, 1);
        ls0 += __shfl_xor_sync(0xffffffffu, ls0, 2);
        ls1 += __shfl_xor_sync(0xffffffffu, ls1, 1);
        ls1 += __shfl_xor_sync(0xffffffffu, ls1, 2);
        li0 = li0 * al0 + ls0;
        li1 = li1 * al1 + ls1;
#pragma unroll
        for (int nt = 0; nt < 8; ++nt) {
            o[nt][0] *= al0; o[nt][1] *= al0;
            o[nt][2] *= al1; o[nt][3] *= al1;
        }

        // ---- P -> hi/lo A-fragments ----
        uint32_t pah[4][4], pal[4][4];
#pragma unroll
        for (int kc = 0; kc < 4; ++kc) {
            split2(s[2 * kc][0],     s[2 * kc][1],     pah[kc][0], pal[kc][0]);
            split2(s[2 * kc][2],     s[2 * kc][3],     pah[kc][1], pal[kc][1]);
            split2(s[2 * kc + 1][0], s[2 * kc + 1][1], pah[kc][2], pal[kc][2]);
            split2(s[2 * kc + 1][2], s[2 * kc + 1][3], pah[kc][3], pal[kc][3]);
        }

        // ---- O += P V ----
#pragma unroll
        for (int g16 = 0; g16 < 4; ++g16) {
            uint32_t go = g16 * (16 * ARS * 2);
#pragma unroll
            for (int kc = 0; kc < 4; ++kc) {
                uint32_t vh[4], vl[4];
                ldsm_x4(vh, adrVH + go + kc * 32);
                ldsm_x4(vl, adrVL + go + kc * 32);
#pragma unroll
                for (int sn = 0; sn < 2; ++sn) {
                    int nt = g16 * 2 + sn;
                    mma_bf16(o[nt], pah[kc], vh[sn * 2], vh[sn * 2 + 1]);
                    mma_bf16(o[nt], pah[kc], vl[sn * 2], vl[sn * 2 + 1]);
                    mma_bf16(o[nt], pal[kc], vh[sn * 2], vh[sn * 2 + 1]);
                }
            }
        }
    }

    // ---- epilogue ----
    float inv0 = 1.f / li0, inv1 = 1.f / li1;
    int r0 = q0 + warp * 16 + g;
    size_t base0 = ((size_t)b * SEQ + r0) * EMB + h * HD;
    size_t base1 = base0 + (size_t)8 * EMB;
#pragma unroll
    for (int nt = 0; nt < 8; ++nt) {
        int d = nt * 8 + tg * 2;
        uint32_t ph, pl;
        split2(o[nt][0] * inv0, o[nt][1] * inv0, ph, pl);
        *(uint32_t*)&g_ahi[base0 + d] = ph;
        *(uint32_t*)&g_alo[base0 + d] = pl;
        split2(o[nt][2] * inv1, o[nt][3] * inv1, ph, pl);
        *(uint32_t*)&g_ahi[base1 + d] = ph;
        *(uint32_t*)&g_alo[base1 + d] = pl;
    }
}

// ---------------------------------------------------------------------------
extern "C" void kernel_launch(void* const* d_in, const int* in_sizes, int n_in,
                              void* d_out, int out_size)
{
    const float* x  = (const float*)d_in[0];
    const float* Wq = (const float*)d_in[1];
    const float* Wk = (const float*)d_in[2];
    const float* Wv = (const float*)d_in[3];
    const float* Wp = (const float*)d_in[4];
    const float* bp = (const float*)d_in[5];
    float* out = (float*)d_out;

    cudaFuncSetAttribute(hmma_gemm,
                         cudaFuncAttributeMaxDynamicSharedMemorySize, GEMM_SMEM);
    cudaFuncSetAttribute(attn_hmma,
                         cudaFuncAttributeMaxDynamicSharedMemorySize, ATTN_SMEM);

    const int n4x = (BATCH * SEQ * EMB) / 4;

    split_x<<<n4x / 256, 256>>>(x);
    conv_wqkv<<<3 * NH * HD, 256>>>(Wq, Wk, Wv);
    conv_wp<<<dim3(EMB / 32, EMB / 32), dim3(32, 8)>>>(Wp);

    // QKV projections -> bf16 hi/lo q, k, v^T   (N = 3072, tiles of 128)
    hmma_gemm<<<dim3(BATCH * SEQ / 128, 3 * NH * HD / 128), 256, GEMM_SMEM>>>(
        nullptr, nullptr, 0);

    // HMMA flash attention, 128-row Q tiles
    attn_hmma<<<dim3(SEQ / 128, NH, BATCH), 256, ATTN_SMEM>>>();

    // Output projection (N = 1024, tiles of 128)
    hmma_gemm<<<dim3(BATCH * SEQ / 128, EMB / 128), 256, GEMM_SMEM>>>(bp, out, 1);
}

// round 16
// speedup vs baseline: 1.1232x; 1.1232x over previous
#include <cuda_runtime.h>
#include <cuda_bf16.h>
#include <cstdint>

#define BATCH 4
#define SEQ   2048
#define EMB   1024
#define NH    16
#define HD    64

// ---------------------------------------------------------------------------
// Scratch (__device__ globals; referenced ONLY from device code)
// ---------------------------------------------------------------------------
__device__ __align__(16) __nv_bfloat16 g_xhi[(size_t)BATCH * SEQ * EMB];
__device__ __align__(16) __nv_bfloat16 g_xlo[(size_t)BATCH * SEQ * EMB];
__device__ __align__(16) __nv_bfloat16 g_ahi[(size_t)BATCH * SEQ * EMB];
__device__ __align__(16) __nv_bfloat16 g_alo[(size_t)BATCH * SEQ * EMB];
__device__ __align__(16) __nv_bfloat16 g_qhi[(size_t)BATCH * NH * SEQ * HD];
__device__ __align__(16) __nv_bfloat16 g_qlo[(size_t)BATCH * NH * SEQ * HD];
__device__ __align__(16) __nv_bfloat16 g_khi[(size_t)BATCH * NH * SEQ * HD];
__device__ __align__(16) __nv_bfloat16 g_klo[(size_t)BATCH * NH * SEQ * HD];
__device__ __align__(16) __nv_bfloat16 g_vthi[(size_t)BATCH * NH * HD * SEQ];
__device__ __align__(16) __nv_bfloat16 g_vtlo[(size_t)BATCH * NH * HD * SEQ];
__device__ __align__(16) __nv_bfloat16 g_bqkv_hi[(size_t)3 * NH * HD * EMB];
__device__ __align__(16) __nv_bfloat16 g_bqkv_lo[(size_t)3 * NH * HD * EMB];
__device__ __align__(16) __nv_bfloat16 g_bp_hi[(size_t)EMB * EMB];
__device__ __align__(16) __nv_bfloat16 g_bp_lo[(size_t)EMB * EMB];

// ---------------------------------------------------------------------------
// Helpers
// ---------------------------------------------------------------------------
__device__ __forceinline__ void split1(float v, __nv_bfloat16& h, __nv_bfloat16& l) {
    h = __float2bfloat16(v);
    l = __float2bfloat16(v - __bfloat162float(h));
}
__device__ __forceinline__ void split2(float x, float y, uint32_t& hp, uint32_t& lp) {
    __nv_bfloat16 hx = __float2bfloat16(x), hy = __float2bfloat16(y);
    __nv_bfloat16 lx = __float2bfloat16(x - __bfloat162float(hx));
    __nv_bfloat16 ly = __float2bfloat16(y - __bfloat162float(hy));
    hp = (uint32_t)__bfloat16_as_ushort(hx) | ((uint32_t)__bfloat16_as_ushort(hy) << 16);
    lp = (uint32_t)__bfloat16_as_ushort(lx) | ((uint32_t)__bfloat16_as_ushort(ly) << 16);
}
__device__ __forceinline__ uint32_t smem_u32(const void* p) {
    uint32_t a;
    asm("{ .reg .u64 t; cvta.to.shared.u64 t, %1; cvt.u32.u64 %0, t; }" : "=r"(a) : "l"(p));
    return a;
}
__device__ __forceinline__ void ldsm_x4(uint32_t* r, uint32_t addr) {
    asm volatile("ldmatrix.sync.aligned.m8n8.x4.shared.b16 {%0,%1,%2,%3}, [%4];"
        : "=r"(r[0]), "=r"(r[1]), "=r"(r[2]), "=r"(r[3]) : "r"(addr));
}
__device__ __forceinline__ void mma_bf16(float* c, const uint32_t* a,
                                         uint32_t b0, uint32_t b1) {
    asm volatile("mma.sync.aligned.m16n8k16.row.col.f32.bf16.bf16.f32 "
        "{%0,%1,%2,%3}, {%4,%5,%6,%7}, {%8,%9}, {%0,%1,%2,%3};"
        : "+f"(c[0]), "+f"(c[1]), "+f"(c[2]), "+f"(c[3])
        : "r"(a[0]), "r"(a[1]), "r"(a[2]), "r"(a[3]), "r"(b0), "r"(b1));
}
__device__ __forceinline__ void cpa16(uint32_t s, const void* g) {
    asm volatile("cp.async.ca.shared.global [%0], [%1], 16;" :: "r"(s), "l"(g));
}
#define CP_COMMIT() asm volatile("cp.async.commit_group;" ::: "memory")
#define CP_WAIT0()  asm volatile("cp.async.wait_group 0;" ::: "memory")

union BF4 { __nv_bfloat16 b[4]; uint2 u; };

// ---------------------------------------------------------------------------
// Conversions (unchanged, validated)
// ---------------------------------------------------------------------------
__global__ void split_x(const float* __restrict__ in)
{
    int i = blockIdx.x * 256 + threadIdx.x;
    float4 v = ((const float4*)in)[i];
    BF4 hh, ll;
    split1(v.x, hh.b[0], ll.b[0]); split1(v.y, hh.b[1], ll.b[1]);
    split1(v.z, hh.b[2], ll.b[2]); split1(v.w, hh.b[3], ll.b[3]);
    ((uint2*)g_xhi)[i] = hh.u;
    ((uint2*)g_xlo)[i] = ll.u;
}

__global__ void conv_wqkv(const float* __restrict__ Wq,
                          const float* __restrict__ Wk,
                          const float* __restrict__ Wv)
{
    int n = blockIdx.x;
    int which = n >> 10, h = (n >> 6) & 15, d = n & 63;
    const float* W = (which == 0) ? Wq : (which == 1) ? Wk : Wv;
    for (int e = threadIdx.x; e < EMB; e += 256) {
        float v = W[((size_t)h * EMB + e) * HD + d];
        __nv_bfloat16 hh, ll;
        split1(v, hh, ll);
        g_bqkv_hi[(size_t)n * EMB + e] = hh;
        g_bqkv_lo[(size_t)n * EMB + e] = ll;
    }
}

__global__ void conv_wp(const float* __restrict__ Wp)
{
    __shared__ float t[32][33];
    int n0 = blockIdx.x * 32, k0 = blockIdx.y * 32;
    for (int r = threadIdx.y; r < 32; r += 8)
        t[r][threadIdx.x] = Wp[(size_t)(k0 + r) * EMB + n0 + threadIdx.x];
    __syncthreads();
    for (int r = threadIdx.y; r < 32; r += 8) {
        float v = t[threadIdx.x][r];
        __nv_bfloat16 hh, ll;
        split1(v, hh, ll);
        g_bp_hi[(size_t)(n0 + r) * EMB + k0 + threadIdx.x] = hh;
        g_bp_lo[(size_t)(n0 + r) * EMB + k0 + threadIdx.x] = ll;
    }
}

// ---------------------------------------------------------------------------
// Split-precision bf16 HMMA GEMM, 128x128 block tile, cp.async 2-stage pipe,
// __launch_bounds__(256, 2) — R15-validated: 404us QKV, tensor 63.4%, occ 24%.
// ---------------------------------------------------------------------------
#define S_AH_B  0
#define S_AL_B  10240
#define S_BH_B  20480
#define S_BL_B  30720
#define STAGE_B 40960
#define GEMM_SMEM (2 * STAGE_B)   // 81920 B
#define NKT 32                    // 1024 / 32

__global__ void __launch_bounds__(256, 2) hmma_gemm(
    const float* __restrict__ bias,
    float* __restrict__ outp, int mode)
{
    extern __shared__ __align__(16) __nv_bfloat16 sm[];
    const int tid = threadIdx.x, wid = tid >> 5, lane = tid & 31;
    const int wm = wid & 1, wn = wid >> 1;          // 2 x 4 warp grid
    const int m0 = blockIdx.x * 128, n0 = blockIdx.y * 128;

    const __nv_bfloat16* __restrict__ Ahi = (mode == 0) ? g_xhi : g_ahi;
    const __nv_bfloat16* __restrict__ Alo = (mode == 0) ? g_xlo : g_alo;
    const __nv_bfloat16* __restrict__ Bhi = (mode == 0) ? g_bqkv_hi : g_bp_hi;
    const __nv_bfloat16* __restrict__ Blo = (mode == 0) ? g_bqkv_lo : g_bp_lo;

    const uint32_t sb = smem_u32(sm);

    const int st_row = tid >> 2, st_c = tid & 3;
    const uint32_t st_dst = st_row * 80 + st_c * 16;
    const size_t gA0 = (size_t)(m0 + st_row) * 128 + st_c;
    const size_t gA1 = (size_t)(m0 + st_row + 64) * 128 + st_c;
    const size_t gB0 = (size_t)(n0 + st_row) * 128 + st_c;
    const size_t gB1 = (size_t)(n0 + st_row + 64) * 128 + st_c;
    const uint32_t st_dst1 = st_dst + 64 * 80;

    const uint32_t a_row = wm * 64 + ((lane >> 3) & 1) * 8 + (lane & 7);
    const uint32_t a_off = a_row * 80 + ((lane >> 4) & 1) * 16;
    const uint32_t b_row = wn * 32 + ((lane >> 4) & 1) * 8 + (lane & 7);
    const uint32_t b_off = b_row * 80 + ((lane >> 3) & 1) * 16;

    float acc[4][4][4];
#pragma unroll
    for (int mt = 0; mt < 4; ++mt)
#pragma unroll
        for (int nt = 0; nt < 4; ++nt)
#pragma unroll
            for (int i = 0; i < 4; ++i) acc[mt][nt][i] = 0.f;

    // ---- prologue: stage 0 ----
    {
        uint32_t so = sb;
        cpa16(so + S_AH_B + st_dst,  (const uint4*)Ahi + gA0);
        cpa16(so + S_AH_B + st_dst1, (const uint4*)Ahi + gA1);
        cpa16(so + S_AL_B + st_dst,  (const uint4*)Alo + gA0);
        cpa16(so + S_AL_B + st_dst1, (const uint4*)Alo + gA1);
        cpa16(so + S_BH_B + st_dst,  (const uint4*)Bhi + gB0);
        cpa16(so + S_BH_B + st_dst1, (const uint4*)Bhi + gB1);
        cpa16(so + S_BL_B + st_dst,  (const uint4*)Blo + gB0);
        cpa16(so + S_BL_B + st_dst1, (const uint4*)Blo + gB1);
        CP_COMMIT();
    }

    for (int kt = 0; kt < NKT; ++kt) {
        CP_WAIT0();
        __syncthreads();
        if (kt + 1 < NKT) {
            uint32_t so = sb + ((kt + 1) & 1) * STAGE_B;
            size_t ko = (size_t)(kt + 1) * 4;
            cpa16(so + S_AH_B + st_dst,  (const uint4*)Ahi + gA0 + ko);
            cpa16(so + S_AH_B + st_dst1, (const uint4*)Ahi + gA1 + ko);
            cpa16(so + S_AL_B + st_dst,  (const uint4*)Alo + gA0 + ko);
            cpa16(so + S_AL_B + st_dst1, (const uint4*)Alo + gA1 + ko);
            cpa16(so + S_BH_B + st_dst,  (const uint4*)Bhi + gB0 + ko);
            cpa16(so + S_BH_B + st_dst1, (const uint4*)Bhi + gB1 + ko);
            cpa16(so + S_BL_B + st_dst,  (const uint4*)Blo + gB0 + ko);
            cpa16(so + S_BL_B + st_dst1, (const uint4*)Blo + gB1 + ko);
            CP_COMMIT();
        }

        uint32_t so = sb + (kt & 1) * STAGE_B;
#pragma unroll
        for (int ks = 0; ks < 2; ++ks) {
            uint32_t aH[4][4], aL[4][4], bH[2][4], bL[2][4];
#pragma unroll
            for (int mt = 0; mt < 4; ++mt) {
                uint32_t off = mt * 1280 + ks * 32;
                ldsm_x4(aH[mt], so + S_AH_B + a_off + off);
                ldsm_x4(aL[mt], so + S_AL_B + a_off + off);
            }
#pragma unroll
            for (int g16 = 0; g16 < 2; ++g16) {
                uint32_t off = g16 * 1280 + ks * 32;
                ldsm_x4(bH[g16], so + S_BH_B + b_off + off);
                ldsm_x4(bL[g16], so + S_BL_B + b_off + off);
            }
#pragma unroll
            for (int mt = 0; mt < 4; ++mt)
#pragma unroll
                for (int nt = 0; nt < 4; ++nt) {
                    uint32_t h0 = bH[nt >> 1][(nt & 1) * 2], h1 = bH[nt >> 1][(nt & 1) * 2 + 1];
                    uint32_t l0 = bL[nt >> 1][(nt & 1) * 2], l1 = bL[nt >> 1][(nt & 1) * 2 + 1];
                    mma_bf16(acc[mt][nt], aH[mt], h0, h1);
                    mma_bf16(acc[mt][nt], aH[mt], l0, l1);
                    mma_bf16(acc[mt][nt], aL[mt], h0, h1);
                }
        }
    }

    // ---- epilogue ----
    const int gr = lane >> 2, cp = (lane & 3) * 2;
#pragma unroll
    for (int mt = 0; mt < 4; ++mt)
#pragma unroll
        for (int nt = 0; nt < 4; ++nt) {
            int ng = n0 + wn * 32 + nt * 8 + cp;
#pragma unroll
            for (int half = 0; half < 2; ++half) {
                int m = m0 + wm * 64 + mt * 16 + gr + half * 8;
                float2 v = make_float2(acc[mt][nt][half * 2], acc[mt][nt][half * 2 + 1]);
                if (mode == 1) {
                    v.x += bias[ng]; v.y += bias[ng + 1];
                    *(float2*)(outp + (size_t)m * EMB + ng) = v;
                } else {
                    int which = ng >> 10, h = (ng >> 6) & 15, d = ng & 63;
                    int b = m >> 11, s = m & 2047;
                    size_t bh = (size_t)b * NH + h;
                    if (which == 0) {
                        uint32_t ph, pl;
                        split2(v.x * 0.125f, v.y * 0.125f, ph, pl);
                        size_t idx = (bh * SEQ + s) * HD + d;
                        *(uint32_t*)&g_qhi[idx] = ph;
                        *(uint32_t*)&g_qlo[idx] = pl;
                    } else if (which == 1) {
                        uint32_t ph, pl;
                        split2(v.x, v.y, ph, pl);
                        size_t idx = (bh * SEQ + s) * HD + d;
                        *(uint32_t*)&g_khi[idx] = ph;
                        *(uint32_t*)&g_klo[idx] = pl;
                    } else {
                        __nv_bfloat16 hx, lx, hy, ly;
                        split1(v.x, hx, lx); split1(v.y, hy, ly);
                        size_t i0 = (bh * HD + d) * SEQ + s;
                        g_vthi[i0] = hx;       g_vtlo[i0] = lx;
                        g_vthi[i0 + SEQ] = hy; g_vtlo[i0 + SEQ] = ly;
                    }
                }
            }
        }
}

// ---------------------------------------------------------------------------
// HMMA causal flash attention — byte-identical to the R11-validated kernel
// (64-row Q tiles, 128 threads; best measured attention: ~360-390us).
// ---------------------------------------------------------------------------
#define ARS 72
#define A_QH 0
#define A_QL 4608
#define A_KH 9216
#define A_KL 13824
#define A_VH 18432
#define A_VL 23040
#define ATTN_SMEM (27648 * 2)   // 55296 B

__global__ __launch_bounds__(128) void attn_hmma()
{
    extern __shared__ __align__(16) __nv_bfloat16 sh[];
    const int tid = threadIdx.x, warp = tid >> 5, lane = tid & 31;
    const int qb = blockIdx.x, h = blockIdx.y, b = blockIdx.z;
    const size_t bh = (size_t)b * NH + h;
    const int q0 = qb * 64;
    const int g = lane >> 2, tg = lane & 3;

    const int a_row = warp * 16 + ((lane >> 3) & 1) * 8 + (lane & 7);
    const int a_kof = ((lane >> 4) & 1) * 8;
    const int b_sub = ((lane >> 4) & 1) * 8 + (lane & 7);
    const int b_kof = ((lane >> 3) & 1) * 8;
    const uint32_t sb = smem_u32(sh);
    const uint32_t adrQH = sb + (A_QH + a_row * ARS + a_kof) * 2;
    const uint32_t adrQL = sb + (A_QL + a_row * ARS + a_kof) * 2;
    const uint32_t adrKH = sb + (A_KH + b_sub * ARS + b_kof) * 2;
    const uint32_t adrKL = sb + (A_KL + b_sub * ARS + b_kof) * 2;
    const uint32_t adrVH = sb + (A_VH + b_sub * ARS + b_kof) * 2;
    const uint32_t adrVL = sb + (A_VL + b_sub * ARS + b_kof) * 2;

    // Stage Q tile once
    {
        const uint4* qh4 = (const uint4*)g_qhi + (bh * SEQ + q0) * 8;
        const uint4* ql4 = (const uint4*)g_qlo + (bh * SEQ + q0) * 8;
        uint4* dh = (uint4*)(sh + A_QH);
        uint4* dl = (uint4*)(sh + A_QL);
        for (int i = tid; i < 512; i += 128) {
            int row = i >> 3, c = i & 7;
            dh[row * 9 + c] = qh4[row * 8 + c];
            dl[row * 9 + c] = ql4[row * 8 + c];
        }
    }

    float o[8][4];
#pragma unroll
    for (int nt = 0; nt < 8; ++nt)
#pragma unroll
        for (int i = 0; i < 4; ++i) o[nt][i] = 0.f;
    float mi0 = -1e30f, mi1 = -1e30f, li0 = 0.f, li1 = 0.f;

    for (int j = 0; j <= qb; ++j) {
        __syncthreads();
        {
            const uint4* kh4 = (const uint4*)g_khi + (bh * SEQ + j * 64) * 8;
            const uint4* kl4 = (const uint4*)g_klo + (bh * SEQ + j * 64) * 8;
            const uint4* vh4 = (const uint4*)g_vthi + bh * HD * 256 + j * 8;
            const uint4* vl4 = (const uint4*)g_vtlo + bh * HD * 256 + j * 8;
            uint4* dkh = (uint4*)(sh + A_KH);
            uint4* dkl = (uint4*)(sh + A_KL);
            uint4* dvh = (uint4*)(sh + A_VH);
            uint4* dvl = (uint4*)(sh + A_VL);
            for (int i = tid; i < 512; i += 128) {
                int row = i >> 3, c = i & 7;
                dkh[row * 9 + c] = kh4[row * 8 + c];
                dkl[row * 9 + c] = kl4[row * 8 + c];
                dvh[row * 9 + c] = vh4[row * 256 + c];
                dvl[row * 9 + c] = vl4[row * 256 + c];
            }
        }
        __syncthreads();

        // ---- S = Q K^T (3-MMA split) ----
        float s[8][4];
#pragma unroll
        for (int nt = 0; nt < 8; ++nt)
#pragma unroll
            for (int i = 0; i < 4; ++i) s[nt][i] = 0.f;

#pragma unroll
        for (int ks = 0; ks < 4; ++ks) {
            uint32_t qh[4], ql[4];
            ldsm_x4(qh, adrQH + ks * 32);
            ldsm_x4(ql, adrQL + ks * 32);
#pragma unroll
            for (int g16 = 0; g16 < 4; ++g16) {
                uint32_t kh[4], kl[4];
                uint32_t go = g16 * (16 * ARS * 2);
                ldsm_x4(kh, adrKH + go + ks * 32);
                ldsm_x4(kl, adrKL + go + ks * 32);
#pragma unroll
                for (int sn = 0; sn < 2; ++sn) {
                    int nt = g16 * 2 + sn;
                    mma_bf16(s[nt], qh, kh[sn * 2], kh[sn * 2 + 1]);
                    mma_bf16(s[nt], qh, kl[sn * 2], kl[sn * 2 + 1]);
                    mma_bf16(s[nt], ql, kh[sn * 2], kh[sn * 2 + 1]);
                }
            }
        }

        // ---- causal mask (diagonal tile only) ----
        if (j == qb) {
            int r0 = warp * 16 + g, r1 = r0 + 8;
#pragma unroll
            for (int nt = 0; nt < 8; ++nt) {
                int c0 = nt * 8 + tg * 2;
                if (c0 > r0)     s[nt][0] = -1e30f;
                if (c0 + 1 > r0) s[nt][1] = -1e30f;
                if (c0 > r1)     s[nt][2] = -1e30f;
                if (c0 + 1 > r1) s[nt][3] = -1e30f;
            }
        }

        // ---- online softmax ----
        float mx0 = -1e30f, mx1 = -1e30f;
#pragma unroll
        for (int nt = 0; nt < 8; ++nt) {
            mx0 = fmaxf(mx0, fmaxf(s[nt][0], s[nt][1]));
            mx1 = fmaxf(mx1, fmaxf(s[nt][2], s[nt][3]));
        }
        mx0 = fmaxf(mx0, __shfl_xor_sync(0xffffffffu, mx0, 1));
        mx0 = fmaxf(mx0, __shfl_xor_sync(0xffffffffu, mx0, 2));
        mx1 = fmaxf(mx1, __shfl_xor_sync(0xffffffffu, mx1, 1));
        mx1 = fmaxf(mx1, __shfl_xor_sync(0xffffffffu, mx1, 2));
        float mn0 = fmaxf(mi0, mx0), mn1 = fmaxf(mi1, mx1);
        float al0 = __expf(mi0 - mn0), al1 = __expf(mi1 - mn1);
        mi0 = mn0; mi1 = mn1;
        float ls0 = 0.f, ls1 = 0.f;
#pragma unroll
        for (int nt = 0; nt < 8; ++nt) {
            s[nt][0] = __expf(s[nt][0] - mn0); ls0 += s[nt][0];
            s[nt][1] = __expf(s[nt][1] - mn0); ls0 += s[nt][1];
            s[nt][2] = __expf(s[nt][2] - mn1); ls1 += s[nt][2];
            s[nt][3] = __expf(s[nt][3] - mn1); ls1 += s[nt][3];
        }
        ls0 += __shfl_xor_sync(0xffffffffu, ls0, 1);
        ls0 += __shfl_xor_sync(0xffffffffu, ls0, 2);
        ls1 += __shfl_xor_sync(0xffffffffu, ls1, 1);
        ls1 += __shfl_xor_sync(0xffffffffu, ls1, 2);
        li0 = li0 * al0 + ls0;
        li1 = li1 * al1 + ls1;
#pragma unroll
        for (int nt = 0; nt < 8; ++nt) {
            o[nt][0] *= al0; o[nt][1] *= al0;
            o[nt][2] *= al1; o[nt][3] *= al1;
        }

        // ---- P -> hi/lo A-fragments ----
        uint32_t pah[4][4], pal[4][4];
#pragma unroll
        for (int kc = 0; kc < 4; ++kc) {
            split2(s[2 * kc][0],     s[2 * kc][1],     pah[kc][0], pal[kc][0]);
            split2(s[2 * kc][2],     s[2 * kc][3],     pah[kc][1], pal[kc][1]);
            split2(s[2 * kc + 1][0], s[2 * kc + 1][1], pah[kc][2], pal[kc][2]);
            split2(s[2 * kc + 1][2], s[2 * kc + 1][3], pah[kc][3], pal[kc][3]);
        }

        // ---- O += P V ----
#pragma unroll
        for (int g16 = 0; g16 < 4; ++g16) {
            uint32_t go = g16 * (16 * ARS * 2);
#pragma unroll
            for (int kc = 0; kc < 4; ++kc) {
                uint32_t vh[4], vl[4];
                ldsm_x4(vh, adrVH + go + kc * 32);
                ldsm_x4(vl, adrVL + go + kc * 32);
#pragma unroll
                for (int sn = 0; sn < 2; ++sn) {
                    int nt = g16 * 2 + sn;
                    mma_bf16(o[nt], pah[kc], vh[sn * 2], vh[sn * 2 + 1]);
                    mma_bf16(o[nt], pah[kc], vl[sn * 2], vl[sn * 2 + 1]);
                    mma_bf16(o[nt], pal[kc], vh[sn * 2], vh[sn * 2 + 1]);
                }
            }
        }
    }

    // ---- epilogue ----
    float inv0 = 1.f / li0, inv1 = 1.f / li1;
    int r0 = q0 + warp * 16 + g;
    size_t base0 = ((size_t)b * SEQ + r0) * EMB + h * HD;
    size_t base1 = base0 + (size_t)8 * EMB;
#pragma unroll
    for (int nt = 0; nt < 8; ++nt) {
        int d = nt * 8 + tg * 2;
        uint32_t ph, pl;
        split2(o[nt][0] * inv0, o[nt][1] * inv0, ph, pl);
        *(uint32_t*)&g_ahi[base0 + d] = ph;
        *(uint32_t*)&g_alo[base0 + d] = pl;
        split2(o[nt][2] * inv1, o[nt][3] * inv1, ph, pl);
        *(uint32_t*)&g_ahi[base1 + d] = ph;
        *(uint32_t*)&g_alo[base1 + d] = pl;
    }
}

// ---------------------------------------------------------------------------
extern "C" void kernel_launch(void* const* d_in, const int* in_sizes, int n_in,
                              void* d_out, int out_size)
{
    const float* x  = (const float*)d_in[0];
    const float* Wq = (const float*)d_in[1];
    const float* Wk = (const float*)d_in[2];
    const float* Wv = (const float*)d_in[3];
    const float* Wp = (const float*)d_in[4];
    const float* bp = (const float*)d_in[5];
    float* out = (float*)d_out;

    cudaFuncSetAttribute(hmma_gemm,
                         cudaFuncAttributeMaxDynamicSharedMemorySize, GEMM_SMEM);
    cudaFuncSetAttribute(attn_hmma,
                         cudaFuncAttributeMaxDynamicSharedMemorySize, ATTN_SMEM);

    const int n4x = (BATCH * SEQ * EMB) / 4;

    split_x<<<n4x / 256, 256>>>(x);
    conv_wqkv<<<3 * NH * HD, 256>>>(Wq, Wk, Wv);
    conv_wp<<<dim3(EMB / 32, EMB / 32), dim3(32, 8)>>>(Wp);

    // QKV projections -> bf16 hi/lo q, k, v^T   (N = 3072, tiles of 128)
    hmma_gemm<<<dim3(BATCH * SEQ / 128, 3 * NH * HD / 128), 256, GEMM_SMEM>>>(
        nullptr, nullptr, 0);

    // HMMA flash attention (R11-validated, 64-row Q tiles)
    attn_hmma<<<dim3(SEQ / 64, NH, BATCH), 128, ATTN_SMEM>>>();

    // Output projection (N = 1024, tiles of 128)
    hmma_gemm<<<dim3(BATCH * SEQ / 128, EMB / 128), 256, GEMM_SMEM>>>(bp, out, 1);
}

// round 17
// speedup vs baseline: 1.1709x; 1.0424x over previous
#include <cuda_runtime.h>
#include <cuda_bf16.h>
#include <cstdint>

#define BATCH 4
#define SEQ   2048
#define EMB   1024
#define NH    16
#define HD    64

// ---------------------------------------------------------------------------
// Scratch (__device__ globals; referenced ONLY from device code)
// ---------------------------------------------------------------------------
__device__ __align__(16) __nv_bfloat16 g_xhi[(size_t)BATCH * SEQ * EMB];
__device__ __align__(16) __nv_bfloat16 g_xlo[(size_t)BATCH * SEQ * EMB];
__device__ __align__(16) __nv_bfloat16 g_ahi[(size_t)BATCH * SEQ * EMB];
__device__ __align__(16) __nv_bfloat16 g_alo[(size_t)BATCH * SEQ * EMB];
__device__ __align__(16) __nv_bfloat16 g_qhi[(size_t)BATCH * NH * SEQ * HD];
__device__ __align__(16) __nv_bfloat16 g_qlo[(size_t)BATCH * NH * SEQ * HD];
__device__ __align__(16) __nv_bfloat16 g_khi[(size_t)BATCH * NH * SEQ * HD];
__device__ __align__(16) __nv_bfloat16 g_klo[(size_t)BATCH * NH * SEQ * HD];
__device__ __align__(16) __nv_bfloat16 g_vthi[(size_t)BATCH * NH * HD * SEQ];
__device__ __align__(16) __nv_bfloat16 g_vtlo[(size_t)BATCH * NH * HD * SEQ];
__device__ __align__(16) __nv_bfloat16 g_bqkv_hi[(size_t)3 * NH * HD * EMB];
__device__ __align__(16) __nv_bfloat16 g_bqkv_lo[(size_t)3 * NH * HD * EMB];
__device__ __align__(16) __nv_bfloat16 g_bp_hi[(size_t)EMB * EMB];
__device__ __align__(16) __nv_bfloat16 g_bp_lo[(size_t)EMB * EMB];

// ---------------------------------------------------------------------------
// Helpers
// ---------------------------------------------------------------------------
__device__ __forceinline__ void split1(float v, __nv_bfloat16& h, __nv_bfloat16& l) {
    h = __float2bfloat16(v);
    l = __float2bfloat16(v - __bfloat162float(h));
}
__device__ __forceinline__ void split2(float x, float y, uint32_t& hp, uint32_t& lp) {
    __nv_bfloat16 hx = __float2bfloat16(x), hy = __float2bfloat16(y);
    __nv_bfloat16 lx = __float2bfloat16(x - __bfloat162float(hx));
    __nv_bfloat16 ly = __float2bfloat16(y - __bfloat162float(hy));
    hp = (uint32_t)__bfloat16_as_ushort(hx) | ((uint32_t)__bfloat16_as_ushort(hy) << 16);
    lp = (uint32_t)__bfloat16_as_ushort(lx) | ((uint32_t)__bfloat16_as_ushort(ly) << 16);
}
__device__ __forceinline__ uint32_t smem_u32(const void* p) {
    uint32_t a;
    asm("{ .reg .u64 t; cvta.to.shared.u64 t, %1; cvt.u32.u64 %0, t; }" : "=r"(a) : "l"(p));
    return a;
}
__device__ __forceinline__ void ldsm_x4(uint32_t* r, uint32_t addr) {
    asm volatile("ldmatrix.sync.aligned.m8n8.x4.shared.b16 {%0,%1,%2,%3}, [%4];"
        : "=r"(r[0]), "=r"(r[1]), "=r"(r[2]), "=r"(r[3]) : "r"(addr));
}
__device__ __forceinline__ void mma_bf16(float* c, const uint32_t* a,
                                         uint32_t b0, uint32_t b1) {
    asm volatile("mma.sync.aligned.m16n8k16.row.col.f32.bf16.bf16.f32 "
        "{%0,%1,%2,%3}, {%4,%5,%6,%7}, {%8,%9}, {%0,%1,%2,%3};"
        : "+f"(c[0]), "+f"(c[1]), "+f"(c[2]), "+f"(c[3])
        : "r"(a[0]), "r"(a[1]), "r"(a[2]), "r"(a[3]), "r"(b0), "r"(b1));
}
__device__ __forceinline__ void cpa16(uint32_t s, const void* g) {
    asm volatile("cp.async.ca.shared.global [%0], [%1], 16;" :: "r"(s), "l"(g));
}
#define CP_COMMIT() asm volatile("cp.async.commit_group;" ::: "memory")
#define CP_WAIT0()  asm volatile("cp.async.wait_group 0;" ::: "memory")
#define CP_WAIT1()  asm volatile("cp.async.wait_group 1;" ::: "memory")

union BF4 { __nv_bfloat16 b[4]; uint2 u; };

// ---------------------------------------------------------------------------
// Conversions (unchanged, validated)
// ---------------------------------------------------------------------------
__global__ void split_x(const float* __restrict__ in)
{
    int i = blockIdx.x * 256 + threadIdx.x;
    float4 v = ((const float4*)in)[i];
    BF4 hh, ll;
    split1(v.x, hh.b[0], ll.b[0]); split1(v.y, hh.b[1], ll.b[1]);
    split1(v.z, hh.b[2], ll.b[2]); split1(v.w, hh.b[3], ll.b[3]);
    ((uint2*)g_xhi)[i] = hh.u;
    ((uint2*)g_xlo)[i] = ll.u;
}

__global__ void conv_wqkv(const float* __restrict__ Wq,
                          const float* __restrict__ Wk,
                          const float* __restrict__ Wv)
{
    int n = blockIdx.x;
    int which = n >> 10, h = (n >> 6) & 15, d = n & 63;
    const float* W = (which == 0) ? Wq : (which == 1) ? Wk : Wv;
    for (int e = threadIdx.x; e < EMB; e += 256) {
        float v = W[((size_t)h * EMB + e) * HD + d];
        __nv_bfloat16 hh, ll;
        split1(v, hh, ll);
        g_bqkv_hi[(size_t)n * EMB + e] = hh;
        g_bqkv_lo[(size_t)n * EMB + e] = ll;
    }
}

__global__ void conv_wp(const float* __restrict__ Wp)
{
    __shared__ float t[32][33];
    int n0 = blockIdx.x * 32, k0 = blockIdx.y * 32;
    for (int r = threadIdx.y; r < 32; r += 8)
        t[r][threadIdx.x] = Wp[(size_t)(k0 + r) * EMB + n0 + threadIdx.x];
    __syncthreads();
    for (int r = threadIdx.y; r < 32; r += 8) {
        float v = t[threadIdx.x][r];
        __nv_bfloat16 hh, ll;
        split1(v, hh, ll);
        g_bp_hi[(size_t)(n0 + r) * EMB + k0 + threadIdx.x] = hh;
        g_bp_lo[(size_t)(n0 + r) * EMB + k0 + threadIdx.x] = ll;
    }
}

// ---------------------------------------------------------------------------
// Split-precision bf16 HMMA GEMM — FROZEN R16 version (404us QKV validated).
// ---------------------------------------------------------------------------
#define S_AH_B  0
#define S_AL_B  10240
#define S_BH_B  20480
#define S_BL_B  30720
#define STAGE_B 40960
#define GEMM_SMEM (2 * STAGE_B)   // 81920 B
#define NKT 32                    // 1024 / 32

__global__ void __launch_bounds__(256, 2) hmma_gemm(
    const float* __restrict__ bias,
    float* __restrict__ outp, int mode)
{
    extern __shared__ __align__(16) __nv_bfloat16 sm[];
    const int tid = threadIdx.x, wid = tid >> 5, lane = tid & 31;
    const int wm = wid & 1, wn = wid >> 1;          // 2 x 4 warp grid
    const int m0 = blockIdx.x * 128, n0 = blockIdx.y * 128;

    const __nv_bfloat16* __restrict__ Ahi = (mode == 0) ? g_xhi : g_ahi;
    const __nv_bfloat16* __restrict__ Alo = (mode == 0) ? g_xlo : g_alo;
    const __nv_bfloat16* __restrict__ Bhi = (mode == 0) ? g_bqkv_hi : g_bp_hi;
    const __nv_bfloat16* __restrict__ Blo = (mode == 0) ? g_bqkv_lo : g_bp_lo;

    const uint32_t sb = smem_u32(sm);

    const int st_row = tid >> 2, st_c = tid & 3;
    const uint32_t st_dst = st_row * 80 + st_c * 16;
    const size_t gA0 = (size_t)(m0 + st_row) * 128 + st_c;
    const size_t gA1 = (size_t)(m0 + st_row + 64) * 128 + st_c;
    const size_t gB0 = (size_t)(n0 + st_row) * 128 + st_c;
    const size_t gB1 = (size_t)(n0 + st_row + 64) * 128 + st_c;
    const uint32_t st_dst1 = st_dst + 64 * 80;

    const uint32_t a_row = wm * 64 + ((lane >> 3) & 1) * 8 + (lane & 7);
    const uint32_t a_off = a_row * 80 + ((lane >> 4) & 1) * 16;
    const uint32_t b_row = wn * 32 + ((lane >> 4) & 1) * 8 + (lane & 7);
    const uint32_t b_off = b_row * 80 + ((lane >> 3) & 1) * 16;

    float acc[4][4][4];
#pragma unroll
    for (int mt = 0; mt < 4; ++mt)
#pragma unroll
        for (int nt = 0; nt < 4; ++nt)
#pragma unroll
            for (int i = 0; i < 4; ++i) acc[mt][nt][i] = 0.f;

    {
        uint32_t so = sb;
        cpa16(so + S_AH_B + st_dst,  (const uint4*)Ahi + gA0);
        cpa16(so + S_AH_B + st_dst1, (const uint4*)Ahi + gA1);
        cpa16(so + S_AL_B + st_dst,  (const uint4*)Alo + gA0);
        cpa16(so + S_AL_B + st_dst1, (const uint4*)Alo + gA1);
        cpa16(so + S_BH_B + st_dst,  (const uint4*)Bhi + gB0);
        cpa16(so + S_BH_B + st_dst1, (const uint4*)Bhi + gB1);
        cpa16(so + S_BL_B + st_dst,  (const uint4*)Blo + gB0);
        cpa16(so + S_BL_B + st_dst1, (const uint4*)Blo + gB1);
        CP_COMMIT();
    }

    for (int kt = 0; kt < NKT; ++kt) {
        CP_WAIT0();
        __syncthreads();
        if (kt + 1 < NKT) {
            uint32_t so = sb + ((kt + 1) & 1) * STAGE_B;
            size_t ko = (size_t)(kt + 1) * 4;
            cpa16(so + S_AH_B + st_dst,  (const uint4*)Ahi + gA0 + ko);
            cpa16(so + S_AH_B + st_dst1, (const uint4*)Ahi + gA1 + ko);
            cpa16(so + S_AL_B + st_dst,  (const uint4*)Alo + gA0 + ko);
            cpa16(so + S_AL_B + st_dst1, (const uint4*)Alo + gA1 + ko);
            cpa16(so + S_BH_B + st_dst,  (const uint4*)Bhi + gB0 + ko);
            cpa16(so + S_BH_B + st_dst1, (const uint4*)Bhi + gB1 + ko);
            cpa16(so + S_BL_B + st_dst,  (const uint4*)Blo + gB0 + ko);
            cpa16(so + S_BL_B + st_dst1, (const uint4*)Blo + gB1 + ko);
            CP_COMMIT();
        }

        uint32_t so = sb + (kt & 1) * STAGE_B;
#pragma unroll
        for (int ks = 0; ks < 2; ++ks) {
            uint32_t aH[4][4], aL[4][4], bH[2][4], bL[2][4];
#pragma unroll
            for (int mt = 0; mt < 4; ++mt) {
                uint32_t off = mt * 1280 + ks * 32;
                ldsm_x4(aH[mt], so + S_AH_B + a_off + off);
                ldsm_x4(aL[mt], so + S_AL_B + a_off + off);
            }
#pragma unroll
            for (int g16 = 0; g16 < 2; ++g16) {
                uint32_t off = g16 * 1280 + ks * 32;
                ldsm_x4(bH[g16], so + S_BH_B + b_off + off);
                ldsm_x4(bL[g16], so + S_BL_B + b_off + off);
            }
#pragma unroll
            for (int mt = 0; mt < 4; ++mt)
#pragma unroll
                for (int nt = 0; nt < 4; ++nt) {
                    uint32_t h0 = bH[nt >> 1][(nt & 1) * 2], h1 = bH[nt >> 1][(nt & 1) * 2 + 1];
                    uint32_t l0 = bL[nt >> 1][(nt & 1) * 2], l1 = bL[nt >> 1][(nt & 1) * 2 + 1];
                    mma_bf16(acc[mt][nt], aH[mt], h0, h1);
                    mma_bf16(acc[mt][nt], aH[mt], l0, l1);
                    mma_bf16(acc[mt][nt], aL[mt], h0, h1);
                }
        }
    }

    const int gr = lane >> 2, cp = (lane & 3) * 2;
#pragma unroll
    for (int mt = 0; mt < 4; ++mt)
#pragma unroll
        for (int nt = 0; nt < 4; ++nt) {
            int ng = n0 + wn * 32 + nt * 8 + cp;
#pragma unroll
            for (int half = 0; half < 2; ++half) {
                int m = m0 + wm * 64 + mt * 16 + gr + half * 8;
                float2 v = make_float2(acc[mt][nt][half * 2], acc[mt][nt][half * 2 + 1]);
                if (mode == 1) {
                    v.x += bias[ng]; v.y += bias[ng + 1];
                    *(float2*)(outp + (size_t)m * EMB + ng) = v;
                } else {
                    int which = ng >> 10, h = (ng >> 6) & 15, d = ng & 63;
                    int b = m >> 11, s = m & 2047;
                    size_t bh = (size_t)b * NH + h;
                    if (which == 0) {
                        uint32_t ph, pl;
                        split2(v.x * 0.125f, v.y * 0.125f, ph, pl);
                        size_t idx = (bh * SEQ + s) * HD + d;
                        *(uint32_t*)&g_qhi[idx] = ph;
                        *(uint32_t*)&g_qlo[idx] = pl;
                    } else if (which == 1) {
                        uint32_t ph, pl;
                        split2(v.x, v.y, ph, pl);
                        size_t idx = (bh * SEQ + s) * HD + d;
                        *(uint32_t*)&g_khi[idx] = ph;
                        *(uint32_t*)&g_klo[idx] = pl;
                    } else {
                        __nv_bfloat16 hx, lx, hy, ly;
                        split1(v.x, hx, lx); split1(v.y, hy, ly);
                        size_t i0 = (bh * HD + d) * SEQ + s;
                        g_vthi[i0] = hx;       g_vtlo[i0] = lx;
                        g_vthi[i0 + SEQ] = hy; g_vtlo[i0 + SEQ] = ly;
                    }
                }
            }
        }
}

// ---------------------------------------------------------------------------
// HMMA causal flash attention, 64-row Q tiles, cp.async phase-pipelined KV:
// K and V single-buffered (smem unchanged -> 4 CTAs/SM) but issued one phase
// early as separate commit groups (order K0,V0,K1,V1,...):
//   V_j issued at tile top, awaited after S+softmax  (covered by ~900 cyc)
//   K_{j+1} issued after S_j's reads,  awaited at next tile's S
// wait_group 1 at each use point leaves exactly the one prefetch in flight.
// Per-warp MMA/softmax math byte-identical to the R11-validated kernel.
// ---------------------------------------------------------------------------
#define ARS 72
#define A_QH 0
#define A_QL 4608
#define A_KH 9216
#define A_KL 13824
#define A_VH 18432
#define A_VL 23040
#define ATTN_SMEM (27648 * 2)   // 55296 B

__global__ __launch_bounds__(128) void attn_hmma()
{
    extern __shared__ __align__(16) __nv_bfloat16 sh[];
    const int tid = threadIdx.x, warp = tid >> 5, lane = tid & 31;
    const int qb = blockIdx.x, h = blockIdx.y, b = blockIdx.z;
    const size_t bh = (size_t)b * NH + h;
    const int q0 = qb * 64;
    const int g = lane >> 2, tg = lane & 3;

    const int a_row = warp * 16 + ((lane >> 3) & 1) * 8 + (lane & 7);
    const int a_kof = ((lane >> 4) & 1) * 8;
    const int b_sub = ((lane >> 4) & 1) * 8 + (lane & 7);
    const int b_kof = ((lane >> 3) & 1) * 8;
    const uint32_t sb = smem_u32(sh);
    const uint32_t adrQH = sb + (A_QH + a_row * ARS + a_kof) * 2;
    const uint32_t adrQL = sb + (A_QL + a_row * ARS + a_kof) * 2;
    const uint32_t adrKH = sb + (A_KH + b_sub * ARS + b_kof) * 2;
    const uint32_t adrKL = sb + (A_KL + b_sub * ARS + b_kof) * 2;
    const uint32_t adrVH = sb + (A_VH + b_sub * ARS + b_kof) * 2;
    const uint32_t adrVL = sb + (A_VL + b_sub * ARS + b_kof) * 2;

    // Global bases (uint4 units)
    const uint4* kh4 = (const uint4*)g_khi + bh * SEQ * 8;
    const uint4* kl4 = (const uint4*)g_klo + bh * SEQ * 8;
    const uint4* vh4 = (const uint4*)g_vthi + bh * HD * 256;
    const uint4* vl4 = (const uint4*)g_vtlo + bh * HD * 256;

    // Per-thread staging coords: 4 uint4 per array per tile
    const int s_row0 = tid >> 3, s_c = tid & 7;     // +16 rows per t

    // K_0 prefetch (group K0)
#pragma unroll
    for (int t = 0; t < 4; ++t) {
        int row = s_row0 + t * 16;
        uint32_t d = (uint32_t)(row * 9 + s_c) * 16;
        cpa16(sb + A_KH * 2 + d, kh4 + (size_t)row * 8 + s_c);
        cpa16(sb + A_KL * 2 + d, kl4 + (size_t)row * 8 + s_c);
    }
    CP_COMMIT();

    // Stage Q tile (regular stores; visible after first loop-top barrier)
    {
        const uint4* qh4 = (const uint4*)g_qhi + (bh * SEQ + q0) * 8;
        const uint4* ql4 = (const uint4*)g_qlo + (bh * SEQ + q0) * 8;
        uint4* dh = (uint4*)(sh + A_QH);
        uint4* dl = (uint4*)(sh + A_QL);
        for (int i = tid; i < 512; i += 128) {
            int row = i >> 3, c = i & 7;
            dh[row * 9 + c] = qh4[row * 8 + c];
            dl[row * 9 + c] = ql4[row * 8 + c];
        }
    }

    float o[8][4];
#pragma unroll
    for (int nt = 0; nt < 8; ++nt)
#pragma unroll
        for (int i = 0; i < 4; ++i) o[nt][i] = 0.f;
    float mi0 = -1e30f, mi1 = -1e30f, li0 = 0.f, li1 = 0.f;

    for (int j = 0; j <= qb; ++j) {
        __syncthreads();                     // closes PV_{j-1} V-reads (and Q stage, j=0)

        // Issue V_j (group; awaited after softmax)
#pragma unroll
        for (int t = 0; t < 4; ++t) {
            int row = s_row0 + t * 16;
            uint32_t d = (uint32_t)(row * 9 + s_c) * 16;
            size_t src = (size_t)row * 256 + j * 8 + s_c;
            cpa16(sb + A_VH * 2 + d, vh4 + src);
            cpa16(sb + A_VL * 2 + d, vl4 + src);
        }
        CP_COMMIT();

        CP_WAIT1();                          // K_j done (V_j still in flight)
        __syncthreads();                     // K visible to all warps

        // ---- S = Q K^T (3-MMA split) ----
        float s[8][4];
#pragma unroll
        for (int nt = 0; nt < 8; ++nt)
#pragma unroll
            for (int i = 0; i < 4; ++i) s[nt][i] = 0.f;

#pragma unroll
        for (int ks = 0; ks < 4; ++ks) {
            uint32_t qh[4], ql[4];
            ldsm_x4(qh, adrQH + ks * 32);
            ldsm_x4(ql, adrQL + ks * 32);
#pragma unroll
            for (int g16 = 0; g16 < 4; ++g16) {
                uint32_t kh[4], kl[4];
                uint32_t go = g16 * (16 * ARS * 2);
                ldsm_x4(kh, adrKH + go + ks * 32);
                ldsm_x4(kl, adrKL + go + ks * 32);
#pragma unroll
                for (int sn = 0; sn < 2; ++sn) {
                    int nt = g16 * 2 + sn;
                    mma_bf16(s[nt], qh, kh[sn * 2], kh[sn * 2 + 1]);
                    mma_bf16(s[nt], qh, kl[sn * 2], kl[sn * 2 + 1]);
                    mma_bf16(s[nt], ql, kh[sn * 2], kh[sn * 2 + 1]);
                }
            }
        }

        __syncthreads();                     // all warps done reading K_j

        // Issue K_{j+1} into the (now free) K buffer; overlaps softmax+PV
        if (j < qb) {
#pragma unroll
            for (int t = 0; t < 4; ++t) {
                int row = s_row0 + t * 16;
                uint32_t d = (uint32_t)(row * 9 + s_c) * 16;
                size_t src = (size_t)((j + 1) * 64 + row) * 8 + s_c;
                cpa16(sb + A_KH * 2 + d, kh4 + src);
                cpa16(sb + A_KL * 2 + d, kl4 + src);
            }
            CP_COMMIT();
        }

        // ---- causal mask (diagonal tile only) ----
        if (j == qb) {
            int r0 = warp * 16 + g, r1 = r0 + 8;
#pragma unroll
            for (int nt = 0; nt < 8; ++nt) {
                int c0 = nt * 8 + tg * 2;
                if (c0 > r0)     s[nt][0] = -1e30f;
                if (c0 + 1 > r0) s[nt][1] = -1e30f;
                if (c0 > r1)     s[nt][2] = -1e30f;
                if (c0 + 1 > r1) s[nt][3] = -1e30f;
            }
        }

        // ---- online softmax ----
        float mx0 = -1e30f, mx1 = -1e30f;
#pragma unroll
        for (int nt = 0; nt < 8; ++nt) {
            mx0 = fmaxf(mx0, fmaxf(s[nt][0], s[nt][1]));
            mx1 = fmaxf(mx1, fmaxf(s[nt][2], s[nt][3]));
        }
        mx0 = fmaxf(mx0, __shfl_xor_sync(0xffffffffu, mx0, 1));
        mx0 = fmaxf(mx0, __shfl_xor_sync(0xffffffffu, mx0, 2));
        mx1 = fmaxf(mx1, __shfl_xor_sync(0xffffffffu, mx1, 1));
        mx1 = fmaxf(mx1, __shfl_xor_sync(0xffffffffu, mx1, 2));
        float mn0 = fmaxf(mi0, mx0), mn1 = fmaxf(mi1, mx1);
        float al0 = __expf(mi0 - mn0), al1 = __expf(mi1 - mn1);
        mi0 = mn0; mi1 = mn1;
        float ls0 = 0.f, ls1 = 0.f;
#pragma unroll
        for (int nt = 0; nt < 8; ++nt) {
            s[nt][0] = __expf(s[nt][0] - mn0); ls0 += s[nt][0];
            s[nt][1] = __expf(s[nt][1] - mn0); ls0 += s[nt][1];
            s[nt][2] = __expf(s[nt][2] - mn1); ls1 += s[nt][2];
            s[nt][3] = __expf(s[nt][3] - mn1); ls1 += s[nt][3];
        }
        ls0 += __shfl_xor_sync(0xffffffffu, ls0, 1);
        ls0 += __shfl_xor_sync(0xffffffffu, ls0, 2);
        ls1 += __shfl_xor_sync(0xffffffffu, ls1, 1);
        ls1 += __shfl_xor_sync(0xffffffffu, ls1, 2);
        li0 = li0 * al0 + ls0;
        li1 = li1 * al1 + ls1;
#pragma unroll
        for (int nt = 0; nt < 8; ++nt) {
            o[nt][0] *= al0; o[nt][1] *= al0;
            o[nt][2] *= al1; o[nt][3] *= al1;
        }

        // ---- P -> hi/lo A-fragments (register work; before the V wait) ----
        uint32_t pah[4][4], pal[4][4];
#pragma unroll
        for (int kc = 0; kc < 4; ++kc) {
            split2(s[2 * kc][0],     s[2 * kc][1],     pah[kc][0], pal[kc][0]);
            split2(s[2 * kc][2],     s[2 * kc][3],     pah[kc][1], pal[kc][1]);
            split2(s[2 * kc + 1][0], s[2 * kc + 1][1], pah[kc][2], pal[kc][2]);
            split2(s[2 * kc + 1][2], s[2 * kc + 1][3], pah[kc][3], pal[kc][3]);
        }

        if (j < qb) { CP_WAIT1(); }          // V_j done (K_{j+1} still in flight)
        else        { CP_WAIT0(); }          // last tile: drain everything
        __syncthreads();                     // V visible to all warps

        // ---- O += P V ----
#pragma unroll
        for (int g16 = 0; g16 < 4; ++g16) {
            uint32_t go = g16 * (16 * ARS * 2);
#pragma unroll
            for (int kc = 0; kc < 4; ++kc) {
                uint32_t vh[4], vl[4];
                ldsm_x4(vh, adrVH + go + kc * 32);
                ldsm_x4(vl, adrVL + go + kc * 32);
#pragma unroll
                for (int sn = 0; sn < 2; ++sn) {
                    int nt = g16 * 2 + sn;
                    mma_bf16(o[nt], pah[kc], vh[sn * 2], vh[sn * 2 + 1]);
                    mma_bf16(o[nt], pah[kc], vl[sn * 2], vl[sn * 2 + 1]);
                    mma_bf16(o[nt], pal[kc], vh[sn * 2], vh[sn * 2 + 1]);
                }
            }
        }
    }

    // ---- epilogue ----
    float inv0 = 1.f / li0, inv1 = 1.f / li1;
    int r0 = q0 + warp * 16 + g;
    size_t base0 = ((size_t)b * SEQ + r0) * EMB + h * HD;
    size_t base1 = base0 + (size_t)8 * EMB;
#pragma unroll
    for (int nt = 0; nt < 8; ++nt) {
        int d = nt * 8 + tg * 2;
        uint32_t ph, pl;
        split2(o[nt][0] * inv0, o[nt][1] * inv0, ph, pl);
        *(uint32_t*)&g_ahi[base0 + d] = ph;
        *(uint32_t*)&g_alo[base0 + d] = pl;
        split2(o[nt][2] * inv1, o[nt][3] * inv1, ph, pl);
        *(uint32_t*)&g_ahi[base1 + d] = ph;
        *(uint32_t*)&g_alo[base1 + d] = pl;
    }
}

// ---------------------------------------------------------------------------
extern "C" void kernel_launch(void* const* d_in, const int* in_sizes, int n_in,
                              void* d_out, int out_size)
{
    const float* x  = (const float*)d_in[0];
    const float* Wq = (const float*)d_in[1];
    const float* Wk = (const float*)d_in[2];
    const float* Wv = (const float*)d_in[3];
    const float* Wp = (const float*)d_in[4];
    const float* bp = (const float*)d_in[5];
    float* out = (float*)d_out;

    cudaFuncSetAttribute(hmma_gemm,
                         cudaFuncAttributeMaxDynamicSharedMemorySize, GEMM_SMEM);
    cudaFuncSetAttribute(attn_hmma,
                         cudaFuncAttributeMaxDynamicSharedMemorySize, ATTN_SMEM);

    const int n4x = (BATCH * SEQ * EMB) / 4;

    split_x<<<n4x / 256, 256>>>(x);
    conv_wqkv<<<3 * NH * HD, 256>>>(Wq, Wk, Wv);
    conv_wp<<<dim3(EMB / 32, EMB / 32), dim3(32, 8)>>>(Wp);

    // QKV projections -> bf16 hi/lo q, k, v^T   (N = 3072, tiles of 128)
    hmma_gemm<<<dim3(BATCH * SEQ / 128, 3 * NH * HD / 128), 256, GEMM_SMEM>>>(
        nullptr, nullptr, 0);

    // HMMA flash attention (64-row Q tiles, cp.async phase-pipelined KV)
    attn_hmma<<<dim3(SEQ / 64, NH, BATCH), 128, ATTN_SMEM>>>();

    // Output projection (N = 1024, tiles of 128)
    hmma_gemm<<<dim3(BATCH * SEQ / 128, EMB / 128), 256, GEMM_SMEM>>>(bp, out, 1);
}